// round 13
// baseline (speedup 1.0000x reference)
#include <cuda_runtime.h>
#include <cuda_bf16.h>
#include <cuda_fp16.h>
#include <math.h>

#define MAXN 50000
#define STRIDE 128                  // fixed CSR row stride (max deg+self ≤ 128)

// ---------------- static device scratch --------------------------------------
__device__ __align__(16) float   g_feat0[MAXN * 64];
__device__ __align__(16) float   g_feat1[MAXN * 64];
__device__ __align__(16) __half2 g_xwh[MAXN * 32];   // fp16 xw rows (64 halves/node)
__device__ float g_as[MAXN];
__device__ float g_ad[MAXN];
__device__ float g_asum[MAXN];
__device__ int   g_cursor[MAXN];
__device__ int2  g_se[MAXN * STRIDE];   // fixed-stride CSR: (src, attr_bits)
__device__ int   g_is64;

__device__ __forceinline__ float siluf(float v) {
    return v / (1.0f + expf(-v));
}

__device__ __forceinline__ int load_idx32(const int* ei32, long long pos, int is64) {
    return ei32[is64 ? 2 * pos : pos];
}

__device__ __forceinline__ unsigned f2tf32(float v) {
    unsigned r;
    asm("cvt.rna.tf32.f32 %0, %1;" : "=r"(r) : "f"(v));
    return r;
}

// ---------------- init + dtype probe ------------------------------------------
__global__ void init_kernel(const unsigned int* __restrict__ w, int n) {
    int i = blockIdx.x * blockDim.x + threadIdx.x;
    if (i < n) { g_cursor[i] = 0; g_asum[i] = 0.0f; }
    if (blockIdx.x == 0 && threadIdx.x < 32) {
        int lane = threadIdx.x;
        unsigned bad = 0;
        #pragma unroll
        for (int k = 0; k < 2; k++) bad |= (w[2 * (lane + 32 * k) + 1] != 0u);
        unsigned any = __ballot_sync(0xffffffffu, bad);
        if (lane == 0) g_is64 = (any == 0u);
    }
}

// ---------------- node MLPs ----------------------------------------------------
__global__ void node_mlp_kernel(
    const float* __restrict__ x, const float* __restrict__ h,
    const float* __restrict__ Wx1, const float* __restrict__ bx1,
    const float* __restrict__ Wx2, const float* __restrict__ bx2,
    const float* __restrict__ Wh1, const float* __restrict__ bh1,
    const float* __restrict__ Wh2, const float* __restrict__ bh2,
    float* __restrict__ feat, int n)
{
    __shared__ float sWx1[3 * 64], sbx1[64], sbx2[32];
    __shared__ float sWh1[5 * 64], sbh1[64], sbh2[32];
    __shared__ float2 sWx2[64 * 16], sWh2[64 * 16];
    for (int i = threadIdx.x; i < 3 * 64; i += blockDim.x) sWx1[i] = Wx1[i];
    for (int i = threadIdx.x; i < 5 * 64; i += blockDim.x) sWh1[i] = Wh1[i];
    for (int i = threadIdx.x; i < 64 * 32; i += blockDim.x) {
        ((float*)sWx2)[i] = Wx2[i];
        ((float*)sWh2)[i] = Wh2[i];
    }
    if (threadIdx.x < 64) { sbx1[threadIdx.x] = bx1[threadIdx.x]; sbh1[threadIdx.x] = bh1[threadIdx.x]; }
    if (threadIdx.x < 32) { sbx2[threadIdx.x] = bx2[threadIdx.x]; sbh2[threadIdx.x] = bh2[threadIdx.x]; }
    __syncthreads();

    int lane = threadIdx.x & 31, wid = threadIdx.x >> 5;
    int nwarps = (blockDim.x >> 5) * gridDim.x;
    float2* feat2 = (float2*)feat;
    for (int node = blockIdx.x * (blockDim.x >> 5) + wid; node < n; node += nwarps) {
        float x0 = x[node * 3 + 0], x1 = x[node * 3 + 1], x2 = x[node * 3 + 2];
        float ha = x0 * sWx1[lane] + x1 * sWx1[64 + lane] + x2 * sWx1[128 + lane] + sbx1[lane];
        float hb = x0 * sWx1[32 + lane] + x1 * sWx1[96 + lane] + x2 * sWx1[160 + lane] + sbx1[32 + lane];
        ha = siluf(ha); hb = siluf(hb);
        float2 acc = make_float2(0.f, 0.f);
        #pragma unroll
        for (int k = 0; k < 64; k++) {
            float hv = __shfl_sync(0xffffffffu, (k < 32) ? ha : hb, k & 31);
            float2 w2 = sWx2[k * 16 + (lane & 15)];
            acc.x += hv * w2.x; acc.y += hv * w2.y;
        }
        float h0 = h[node * 5 + 0], h1 = h[node * 5 + 1], h2 = h[node * 5 + 2],
              h3 = h[node * 5 + 3], h4 = h[node * 5 + 4];
        float ga = h0 * sWh1[lane] + h1 * sWh1[64 + lane] + h2 * sWh1[128 + lane]
                 + h3 * sWh1[192 + lane] + h4 * sWh1[256 + lane] + sbh1[lane];
        float gb = h0 * sWh1[32 + lane] + h1 * sWh1[96 + lane] + h2 * sWh1[160 + lane]
                 + h3 * sWh1[224 + lane] + h4 * sWh1[288 + lane] + sbh1[32 + lane];
        ga = siluf(ga); gb = siluf(gb);
        float2 acch = make_float2(0.f, 0.f);
        #pragma unroll
        for (int k = 0; k < 64; k++) {
            float hv = __shfl_sync(0xffffffffu, (k < 32) ? ga : gb, k & 31);
            float2 w2 = sWh2[k * 16 + (lane & 15)];
            acch.x += hv * w2.x; acch.y += hv * w2.y;
        }
        int p = lane & 15;
        if (lane < 16) {
            feat2[node * 32 + p] = make_float2(acc.x + sbx2[2 * p], acc.y + sbx2[2 * p + 1]);
        } else {
            feat2[node * 32 + 16 + p] = make_float2(acch.x + sbh2[2 * p], acch.y + sbh2[2 * p + 1]);
        }
    }
}

// ---------------- CSR build: direct scatter + attr-sum atomics ----------------
__global__ void scatter_kernel(const int* __restrict__ ei32,
                               const float* __restrict__ ea, int E, int n)
{
    int is64 = g_is64;
    int t = blockIdx.x * blockDim.x + threadIdx.x;
    if (t < E) {
        int d = load_idx32(ei32, (long long)E + t, is64);
        int s = load_idx32(ei32, t, is64);
        if ((unsigned)d < (unsigned)n && (unsigned)s < (unsigned)n) {
            float attr = __ldg(&ea[t]);
            int pos = atomicAdd(&g_cursor[d], 1);
            atomicAdd(&g_asum[d], attr);
            if (pos < STRIDE - 1)
                g_se[d * STRIDE + pos] = make_int2(s, __float_as_int(attr));
        }
    }
}

// self-loop appended at slot deg (thread-per-node; mean from atomic sum)
__global__ void selfloop_kernel(int n) {
    int i = blockIdx.x * blockDim.x + threadIdx.x;
    if (i < n) {
        int deg = g_cursor[i];
        if (deg > STRIDE - 1) deg = STRIDE - 1;
        float mean = g_asum[i] / fmaxf((float)deg, 1.0f);
        g_se[i * STRIDE + deg] = make_int2(i, __float_as_int(mean));
        g_cursor[i] = deg + 1;
    }
}

// ---------------- per-layer: xw = feat @ W via TF32 MMA; exact fp32 logits ----
// xw: single TF32 MMA (noise attenuated downstream). a_s/a_d: fp32 dot with
// precomputed va = W@asrc (ROW dot: va[k] = sum_j W[k][j]*asrc[j]).
__global__ void xw_mma_kernel(const float* __restrict__ W,
                              const float* __restrict__ asrc,
                              const float* __restrict__ adst,
                              const float* __restrict__ feat, int n)
{
    __shared__ uint2 sWp[64 * 32];             // W tf32 fragments
    __shared__ float s_va[64], s_vd[64];       // va[k] = W[k][:]·asrc, vd[k] = W[k][:]·adst
    {
        int tid = threadIdx.x;
        for (int idx = tid; idx < 4096; idx += blockDim.x) {
            int k = idx >> 6, nn = idx & 63;
            int kstep = k >> 3, kr = k & 7;
            int nt = nn >> 3, nc = nn & 7;
            int lane_t = nc * 4 + (kr & 3);
            unsigned v = f2tf32(W[k * 64 + nn]);
            ((unsigned*)&sWp[(kstep * 8 + nt) * 32 + lane_t])[(kr >> 2) & 1] = v;
        }
        if (tid < 64) {
            // ROW dot: a_s = feat @ (W @ asrc)  =>  va[k] = sum_j W[k][j]*asrc[j]
            float sa = 0.f, sd = 0.f;
            #pragma unroll 8
            for (int j = 0; j < 64; j++) {
                float w = W[tid * 64 + j];
                sa += w * asrc[j];
                sd += w * adst[j];
            }
            s_va[tid] = sa;
            s_vd[tid] = sd;
        }
    }
    __syncthreads();

    int lane = threadIdx.x & 31, warp = threadIdx.x >> 5;
    int q = lane & 3;
    int g = lane >> 2;
    int row0 = blockIdx.x * 128 + warp * 16 + g;
    int row1 = row0 + 8;
    bool v0 = row0 < n, v1 = row1 < n;

    float c[8][4];
    #pragma unroll
    for (int t = 0; t < 8; t++) { c[t][0] = c[t][1] = c[t][2] = c[t][3] = 0.f; }

    const float* f0p = feat + (long long)row0 * 64;
    const float* f1p = feat + (long long)row1 * 64;

    float ps0 = 0.f, pd0 = 0.f, ps1 = 0.f, pd1 = 0.f;

    #pragma unroll
    for (int ks = 0; ks < 8; ks++) {
        int col = ks * 8 + q;
        float av0 = v0 ? f0p[col]     : 0.f;
        float av1 = v1 ? f1p[col]     : 0.f;
        float av2 = v0 ? f0p[col + 4] : 0.f;
        float av3 = v1 ? f1p[col + 4] : 0.f;
        // exact fp32 logit accumulation
        float vaL = s_va[col], vaH = s_va[col + 4];
        float vdL = s_vd[col], vdH = s_vd[col + 4];
        ps0 += av0 * vaL + av2 * vaH;
        pd0 += av0 * vdL + av2 * vdH;
        ps1 += av1 * vaL + av3 * vaH;
        pd1 += av1 * vdL + av3 * vdH;

        unsigned a0 = f2tf32(av0), a1 = f2tf32(av1), a2 = f2tf32(av2), a3 = f2tf32(av3);
        #pragma unroll
        for (int nt = 0; nt < 8; nt++) {
            uint2 b = sWp[(ks * 8 + nt) * 32 + lane];
            asm volatile(
                "mma.sync.aligned.m16n8k8.row.col.f32.tf32.tf32.f32 "
                "{%0,%1,%2,%3}, {%4,%5,%6,%7}, {%8,%9}, {%0,%1,%2,%3};"
                : "+f"(c[nt][0]), "+f"(c[nt][1]), "+f"(c[nt][2]), "+f"(c[nt][3])
                : "r"(a0), "r"(a1), "r"(a2), "r"(a3), "r"(b.x), "r"(b.y));
        }
    }

    // epilogue: store fp16 xw
    #pragma unroll
    for (int nt = 0; nt < 8; nt++) {
        if (v0) g_xwh[row0 * 32 + nt * 4 + q] = __floats2half2_rn(c[nt][0], c[nt][1]);
        if (v1) g_xwh[row1 * 32 + nt * 4 + q] = __floats2half2_rn(c[nt][2], c[nt][3]);
    }
    #pragma unroll
    for (int o = 1; o < 4; o <<= 1) {
        ps0 += __shfl_xor_sync(0xffffffffu, ps0, o);
        pd0 += __shfl_xor_sync(0xffffffffu, pd0, o);
        ps1 += __shfl_xor_sync(0xffffffffu, ps1, o);
        pd1 += __shfl_xor_sync(0xffffffffu, pd1, o);
    }
    if (q == 0) {
        if (v0) { g_as[row0] = ps0; g_ad[row0] = pd0; }
        if (v1) { g_as[row1] = ps1; g_ad[row1] = pd1; }
    }
}

// ---------------- per-layer: fused softmax attention + aggregation ------------
__global__ void gat_edge_kernel(const float* __restrict__ We,
                                const float* __restrict__ aedge,
                                const float* __restrict__ bias,
                                float* __restrict__ out, int n)
{
    const unsigned F = 0xffffffffu;
    int lane = threadIdx.x & 31, wid = threadIdx.x >> 5;
    float cp = We[2 * lane] * aedge[2 * lane] + We[2 * lane + 1] * aedge[2 * lane + 1];
    #pragma unroll
    for (int o = 16; o; o >>= 1) cp += __shfl_xor_sync(F, cp, o);
    float c = cp;

    const uint2* xh = (const uint2*)g_xwh;
    float4* out4 = (float4*)out;
    int nwarps = (blockDim.x >> 5) * gridDim.x;
    int p = lane & 15;
    int half = lane >> 4;

    for (int node = blockIdx.x * (blockDim.x >> 5) + wid; node < n; node += nwarps) {
        int rs = node * STRIDE;
        int len = g_cursor[node];           // deg + 1 (incl. self-loop), <= 128
        int re = rs + len;
        float adn = g_ad[node];

        float a[4]; int srcs[4];
        float mx = -1e30f;
        #pragma unroll
        for (int s = 0; s < 4; s++) {
            int i = rs + s * 32 + lane;
            float al = -1e30f; int sv = 0;
            if (i < re) {
                int2 se = __ldg(&g_se[i]);
                sv = se.x;
                al = g_as[sv] + adn + c * __int_as_float(se.y);
                al = (al > 0.0f) ? al : 0.2f * al;
            }
            a[s] = al; srcs[s] = sv;
            mx = fmaxf(mx, al);
        }
        #pragma unroll
        for (int o = 16; o; o >>= 1) mx = fmaxf(mx, __shfl_xor_sync(F, mx, o));

        float sum = 0.0f;
        #pragma unroll
        for (int s = 0; s < 4; s++) {
            int i = rs + s * 32 + lane;
            float e = (i < re) ? expf(a[s] - mx) : 0.0f;
            a[s] = e;
            sum += e;
        }
        #pragma unroll
        for (int o = 16; o; o >>= 1) sum += __shfl_xor_sync(F, sum, o);
        float inv = 1.0f / fmaxf(sum, 1e-16f);

        float4 acc = make_float4(0.f, 0.f, 0.f, 0.f);
        #pragma unroll
        for (int s = 0; s < 4; s++) {
            int base = s * 32;
            if (base >= len) break;
            int m = len - base; if (m > 32) m = 32;
            int j = 0;
            for (; j + 8 <= m; j += 8) {
                float w0 = __shfl_sync(F, a[s], j + half);
                float w1 = __shfl_sync(F, a[s], j + 2 + half);
                float w2 = __shfl_sync(F, a[s], j + 4 + half);
                float w3 = __shfl_sync(F, a[s], j + 6 + half);
                int v0 = __shfl_sync(F, srcs[s], j + half);
                int v1 = __shfl_sync(F, srcs[s], j + 2 + half);
                int v2 = __shfl_sync(F, srcs[s], j + 4 + half);
                int v3 = __shfl_sync(F, srcs[s], j + 6 + half);
                uint2 q0 = xh[v0 * 16 + p];
                uint2 q1 = xh[v1 * 16 + p];
                uint2 q2 = xh[v2 * 16 + p];
                uint2 q3 = xh[v3 * 16 + p];
                float2 l0 = __half22float2(*(__half2*)&q0.x), h0 = __half22float2(*(__half2*)&q0.y);
                float2 l1 = __half22float2(*(__half2*)&q1.x), h1 = __half22float2(*(__half2*)&q1.y);
                float2 l2 = __half22float2(*(__half2*)&q2.x), h2 = __half22float2(*(__half2*)&q2.y);
                float2 l3 = __half22float2(*(__half2*)&q3.x), h3 = __half22float2(*(__half2*)&q3.y);
                acc.x += w0 * l0.x; acc.y += w0 * l0.y; acc.z += w0 * h0.x; acc.w += w0 * h0.y;
                acc.x += w1 * l1.x; acc.y += w1 * l1.y; acc.z += w1 * h1.x; acc.w += w1 * h1.y;
                acc.x += w2 * l2.x; acc.y += w2 * l2.y; acc.z += w2 * h2.x; acc.w += w2 * h2.y;
                acc.x += w3 * l3.x; acc.y += w3 * l3.y; acc.z += w3 * h3.x; acc.w += w3 * h3.y;
            }
            for (; j < m; j += 2) {
                int jj = j + half;
                int sl = (jj < m) ? jj : 0;
                float w = __shfl_sync(F, a[s], sl);
                int   v = __shfl_sync(F, srcs[s], sl);
                if (jj >= m) w = 0.0f;
                uint2 qq = xh[v * 16 + p];
                float2 lo = __half22float2(*(__half2*)&qq.x), hi = __half22float2(*(__half2*)&qq.y);
                acc.x += w * lo.x; acc.y += w * lo.y; acc.z += w * hi.x; acc.w += w * hi.y;
            }
        }
        acc.x += __shfl_xor_sync(F, acc.x, 16);
        acc.y += __shfl_xor_sync(F, acc.y, 16);
        acc.z += __shfl_xor_sync(F, acc.z, 16);
        acc.w += __shfl_xor_sync(F, acc.w, 16);
        if (lane < 16) {
            float4 b4 = ((const float4*)bias)[p];
            out4[node * 16 + p] = make_float4(acc.x * inv + b4.x, acc.y * inv + b4.y,
                                              acc.z * inv + b4.z, acc.w * inv + b4.w);
        }
    }
}

// ---------------- final head ---------------------------------------------------
__global__ void out_mlp_kernel(const float* __restrict__ Wm1,
                               const float* __restrict__ bm1,
                               const float* __restrict__ Wm2,
                               const float* __restrict__ bm2,
                               const float* __restrict__ feat,
                               float* __restrict__ out, int n)
{
    __shared__ float2 sW1[64 * 32];
    __shared__ float sb1[64], sW2[64 * 24], sb2[24];
    __shared__ float2 hs[8][32];
    for (int i = threadIdx.x; i < 64 * 64; i += blockDim.x) ((float*)sW1)[i] = Wm1[i];
    for (int i = threadIdx.x; i < 64 * 24; i += blockDim.x) sW2[i] = Wm2[i];
    if (threadIdx.x < 64) sb1[threadIdx.x] = bm1[threadIdx.x];
    if (threadIdx.x < 24) sb2[threadIdx.x] = bm2[threadIdx.x];
    __syncthreads();

    const float2* feat2 = (const float2*)feat;
    int lane = threadIdx.x & 31, wid = threadIdx.x >> 5;
    int nwarps = (blockDim.x >> 5) * gridDim.x;
    for (int node = blockIdx.x * (blockDim.x >> 5) + wid; node < n; node += nwarps) {
        float2 f = feat2[node * 32 + lane];
        float2 hid = make_float2(sb1[2 * lane], sb1[2 * lane + 1]);
        #pragma unroll
        for (int k = 0; k < 64; k++) {
            float fv = __shfl_sync(0xffffffffu, (k & 1) ? f.y : f.x, k >> 1);
            float2 w2 = sW1[k * 32 + lane];
            hid.x += fv * w2.x;
            hid.y += fv * w2.y;
        }
        hid.x = siluf(hid.x);
        hid.y = siluf(hid.y);
        hs[wid][lane] = hid;
        __syncwarp();
        if (lane < 24) {
            float a = sb2[lane];
            #pragma unroll
            for (int k2 = 0; k2 < 32; k2++) {
                float2 hv = hs[wid][k2];
                a += hv.x * sW2[(2 * k2) * 24 + lane];
                a += hv.y * sW2[(2 * k2 + 1) * 24 + lane];
            }
            out[node * 24 + lane] = a;
        }
        __syncwarp();
    }
}

// ---------------- launch --------------------------------------------------------
extern "C" void kernel_launch(void* const* d_in, const int* in_sizes, int n_in,
                              void* d_out, int out_size)
{
    const float*     x   = (const float*)d_in[0];
    const float*     h   = (const float*)d_in[1];
    const float*     ea  = (const float*)d_in[2];
    const void*      ei  = d_in[3];
    const float *Wx1 = (const float*)d_in[4],  *bx1 = (const float*)d_in[5];
    const float *Wx2 = (const float*)d_in[6],  *bx2 = (const float*)d_in[7];
    const float *Wh1 = (const float*)d_in[8],  *bh1 = (const float*)d_in[9];
    const float *Wh2 = (const float*)d_in[10], *bh2 = (const float*)d_in[11];
    const float *gW  = (const float*)d_in[12];
    const float *gas = (const float*)d_in[13];
    const float *gad = (const float*)d_in[14];
    const float *gae = (const float*)d_in[15];
    const float *gWe = (const float*)d_in[16];
    const float *gb  = (const float*)d_in[17];
    const float *Wm1 = (const float*)d_in[18], *bm1 = (const float*)d_in[19];
    const float *Wm2 = (const float*)d_in[20], *bm2 = (const float*)d_in[21];
    float* out = (float*)d_out;

    const int n = in_sizes[0] / 3;
    const int E = in_sizes[2];

    float* feat0; cudaGetSymbolAddress((void**)&feat0, g_feat0);
    float* feat1; cudaGetSymbolAddress((void**)&feat1, g_feat1);

    const int TB = 256;
    const int WARP_BLOCKS = 1480;

    init_kernel<<<(n + TB - 1) / TB, TB>>>((const unsigned int*)ei, n);
    node_mlp_kernel<<<WARP_BLOCKS, TB>>>(x, h, Wx1, bx1, Wx2, bx2, Wh1, bh1, Wh2, bh2, feat0, n);
    scatter_kernel<<<(E + TB - 1) / TB, TB>>>((const int*)ei, ea, E, n);
    selfloop_kernel<<<(n + TB - 1) / TB, TB>>>(n);

    float* fin = feat0;
    float* fout = feat1;
    for (int l = 0; l < 3; l++) {
        xw_mma_kernel<<<(n + 127) / 128, TB>>>(gW + l * 64 * 64, gas + l * 64, gad + l * 64, fin, n);
        gat_edge_kernel<<<(n + 7) / 8, TB>>>(gWe + l * 64, gae + l * 64, gb + l * 64, fout, n);
        float* t = fin; fin = fout; fout = t;
    }
    out_mlp_kernel<<<WARP_BLOCKS, TB>>>(Wm1, bm1, Wm2, bm2, fin, out, n);
}

// round 14
// speedup vs baseline: 1.1563x; 1.1563x over previous
#include <cuda_runtime.h>
#include <cuda_bf16.h>
#include <cuda_fp16.h>
#include <math.h>

#define MAXN 50000
#define STRIDE 128                  // fixed CSR row stride (max deg+self ≤ 128)

// ---------------- static device scratch --------------------------------------
__device__ __align__(16) float   g_feat0[MAXN * 64];
__device__ __align__(16) float   g_feat1[MAXN * 64];
__device__ __align__(16) __half2 g_xwh[MAXN * 32];   // fp16 xw rows (64 halves/node)
__device__ float g_as[MAXN];
__device__ float g_ad[MAXN];
__device__ float g_asum[MAXN];
__device__ int   g_cursor[MAXN];
__device__ int2  g_se[MAXN * STRIDE];   // fixed-stride CSR: (src, attr_bits)
__device__ int   g_is64;

__device__ __forceinline__ float siluf(float v) {
    return v / (1.0f + expf(-v));
}

__device__ __forceinline__ int load_idx32(const int* ei32, long long pos, int is64) {
    return ei32[is64 ? 2 * pos : pos];
}

__device__ __forceinline__ unsigned f2tf32(float v) {
    unsigned r;
    asm("cvt.rna.tf32.f32 %0, %1;" : "=r"(r) : "f"(v));
    return r;
}

// ---------------- node MLPs + fused init/dtype-probe ---------------------------
__global__ void node_mlp_kernel(
    const unsigned int* __restrict__ eiw,
    const float* __restrict__ x, const float* __restrict__ h,
    const float* __restrict__ Wx1, const float* __restrict__ bx1,
    const float* __restrict__ Wx2, const float* __restrict__ bx2,
    const float* __restrict__ Wh1, const float* __restrict__ bh1,
    const float* __restrict__ Wh2, const float* __restrict__ bh2,
    float* __restrict__ feat, int n)
{
    // fused init: zero cursors/asum (grid-stride over nodes)
    for (int i = blockIdx.x * blockDim.x + threadIdx.x; i < n; i += blockDim.x * gridDim.x) {
        g_cursor[i] = 0;
        g_asum[i] = 0.0f;
    }
    // dtype probe (block 0, warp 0)
    if (blockIdx.x == 0 && threadIdx.x < 32) {
        int lane = threadIdx.x;
        unsigned bad = 0;
        #pragma unroll
        for (int k = 0; k < 2; k++) bad |= (eiw[2 * (lane + 32 * k) + 1] != 0u);
        unsigned any = __ballot_sync(0xffffffffu, bad);
        if (lane == 0) g_is64 = (any == 0u);
    }

    __shared__ float sWx1[3 * 64], sbx1[64], sbx2[32];
    __shared__ float sWh1[5 * 64], sbh1[64], sbh2[32];
    __shared__ float2 sWx2[64 * 16], sWh2[64 * 16];
    for (int i = threadIdx.x; i < 3 * 64; i += blockDim.x) sWx1[i] = Wx1[i];
    for (int i = threadIdx.x; i < 5 * 64; i += blockDim.x) sWh1[i] = Wh1[i];
    for (int i = threadIdx.x; i < 64 * 32; i += blockDim.x) {
        ((float*)sWx2)[i] = Wx2[i];
        ((float*)sWh2)[i] = Wh2[i];
    }
    if (threadIdx.x < 64) { sbx1[threadIdx.x] = bx1[threadIdx.x]; sbh1[threadIdx.x] = bh1[threadIdx.x]; }
    if (threadIdx.x < 32) { sbx2[threadIdx.x] = bx2[threadIdx.x]; sbh2[threadIdx.x] = bh2[threadIdx.x]; }
    __syncthreads();

    int lane = threadIdx.x & 31, wid = threadIdx.x >> 5;
    int nwarps = (blockDim.x >> 5) * gridDim.x;
    float2* feat2 = (float2*)feat;

    // 2 nodes per warp iteration: weight LDS amortized
    for (int base = (blockIdx.x * (blockDim.x >> 5) + wid) * 2; base < n; base += nwarps * 2) {
        float ha[2], hb[2], ga[2], gb[2];
        #pragma unroll
        for (int m = 0; m < 2; m++) {
            int node = base + m;
            if (node < n) {
                float x0 = x[node * 3 + 0], x1 = x[node * 3 + 1], x2 = x[node * 3 + 2];
                ha[m] = siluf(x0 * sWx1[lane] + x1 * sWx1[64 + lane] + x2 * sWx1[128 + lane] + sbx1[lane]);
                hb[m] = siluf(x0 * sWx1[32 + lane] + x1 * sWx1[96 + lane] + x2 * sWx1[160 + lane] + sbx1[32 + lane]);
                float h0 = h[node * 5 + 0], h1 = h[node * 5 + 1], h2 = h[node * 5 + 2],
                      h3 = h[node * 5 + 3], h4 = h[node * 5 + 4];
                ga[m] = siluf(h0 * sWh1[lane] + h1 * sWh1[64 + lane] + h2 * sWh1[128 + lane]
                            + h3 * sWh1[192 + lane] + h4 * sWh1[256 + lane] + sbh1[lane]);
                gb[m] = siluf(h0 * sWh1[32 + lane] + h1 * sWh1[96 + lane] + h2 * sWh1[160 + lane]
                            + h3 * sWh1[224 + lane] + h4 * sWh1[288 + lane] + sbh1[32 + lane]);
            } else {
                ha[m] = hb[m] = ga[m] = gb[m] = 0.f;
            }
        }
        float2 accx[2] = {make_float2(0.f, 0.f), make_float2(0.f, 0.f)};
        float2 acch[2] = {make_float2(0.f, 0.f), make_float2(0.f, 0.f)};
        int pl = lane & 15;
        #pragma unroll
        for (int k = 0; k < 64; k++) {
            float2 wx = sWx2[k * 16 + pl];
            float2 wh = sWh2[k * 16 + pl];
            #pragma unroll
            for (int m = 0; m < 2; m++) {
                float hvx = __shfl_sync(0xffffffffu, (k < 32) ? ha[m] : hb[m], k & 31);
                float hvh = __shfl_sync(0xffffffffu, (k < 32) ? ga[m] : gb[m], k & 31);
                accx[m].x += hvx * wx.x; accx[m].y += hvx * wx.y;
                acch[m].x += hvh * wh.x; acch[m].y += hvh * wh.y;
            }
        }
        #pragma unroll
        for (int m = 0; m < 2; m++) {
            int node = base + m;
            if (node >= n) break;
            if (lane < 16) {
                feat2[node * 32 + pl] = make_float2(accx[m].x + sbx2[2 * pl], accx[m].y + sbx2[2 * pl + 1]);
            } else {
                feat2[node * 32 + 16 + pl] = make_float2(acch[m].x + sbh2[2 * pl], acch[m].y + sbh2[2 * pl + 1]);
            }
        }
    }
}

// ---------------- CSR build: direct scatter + attr-sum atomics ----------------
__global__ void scatter_kernel(const int* __restrict__ ei32,
                               const float* __restrict__ ea, int E, int n)
{
    int is64 = g_is64;
    int t = blockIdx.x * blockDim.x + threadIdx.x;
    if (t < E) {
        int d = load_idx32(ei32, (long long)E + t, is64);
        int s = load_idx32(ei32, t, is64);
        if ((unsigned)d < (unsigned)n && (unsigned)s < (unsigned)n) {
            float attr = __ldg(&ea[t]);
            int pos = atomicAdd(&g_cursor[d], 1);
            atomicAdd(&g_asum[d], attr);
            if (pos < STRIDE - 1)
                g_se[d * STRIDE + pos] = make_int2(s, __float_as_int(attr));
        }
    }
}

// self-loop appended at slot deg (thread-per-node; mean from atomic sum)
__global__ void selfloop_kernel(int n) {
    int i = blockIdx.x * blockDim.x + threadIdx.x;
    if (i < n) {
        int deg = g_cursor[i];
        if (deg > STRIDE - 1) deg = STRIDE - 1;
        float mean = g_asum[i] / fmaxf((float)deg, 1.0f);
        g_se[i * STRIDE + deg] = make_int2(i, __float_as_int(mean));
        g_cursor[i] = deg + 1;
    }
}

// ---------------- per-layer: xw = feat @ W via compensated TF32 MMA -----------
// 3-MMA split: c += ah*wh + al*wh + ah*wl  (error ~2^-22); a_s/a_d from fp32 accs.
__global__ void xw_mma_kernel(const float* __restrict__ W,
                              const float* __restrict__ asrc,
                              const float* __restrict__ adst,
                              const float* __restrict__ feat, int n)
{
    __shared__ uint2 sWh[64 * 32], sWl[64 * 32];
    __shared__ float s_as[64], s_ad[64];
    {
        int tid = threadIdx.x;
        for (int idx = tid; idx < 4096; idx += blockDim.x) {
            int k = idx >> 6, nn = idx & 63;
            int kstep = k >> 3, kr = k & 7;
            int nt = nn >> 3, nc = nn & 7;
            int lane_t = nc * 4 + (kr & 3);
            float w = W[k * 64 + nn];
            unsigned hi = f2tf32(w);
            unsigned lo = f2tf32(w - __uint_as_float(hi));
            int slot = (kstep * 8 + nt) * 32 + lane_t;
            int sub = (kr >> 2) & 1;
            ((unsigned*)&sWh[slot])[sub] = hi;
            ((unsigned*)&sWl[slot])[sub] = lo;
        }
        if (tid < 64) { s_as[tid] = asrc[tid]; s_ad[tid] = adst[tid]; }
    }
    __syncthreads();

    int lane = threadIdx.x & 31, warp = threadIdx.x >> 5;
    int q = lane & 3;
    int g = lane >> 2;
    int row0 = blockIdx.x * 128 + warp * 16 + g;
    int row1 = row0 + 8;
    bool v0 = row0 < n, v1 = row1 < n;

    float c[8][4];
    #pragma unroll
    for (int t = 0; t < 8; t++) { c[t][0] = c[t][1] = c[t][2] = c[t][3] = 0.f; }

    const float* f0p = feat + (long long)row0 * 64;
    const float* f1p = feat + (long long)row1 * 64;

    #pragma unroll
    for (int ks = 0; ks < 8; ks++) {
        int col = ks * 8 + q;
        float av0 = v0 ? f0p[col]     : 0.f;
        float av1 = v1 ? f1p[col]     : 0.f;
        float av2 = v0 ? f0p[col + 4] : 0.f;
        float av3 = v1 ? f1p[col + 4] : 0.f;
        unsigned a0h = f2tf32(av0), a1h = f2tf32(av1), a2h = f2tf32(av2), a3h = f2tf32(av3);
        unsigned a0l = f2tf32(av0 - __uint_as_float(a0h));
        unsigned a1l = f2tf32(av1 - __uint_as_float(a1h));
        unsigned a2l = f2tf32(av2 - __uint_as_float(a2h));
        unsigned a3l = f2tf32(av3 - __uint_as_float(a3h));
        #pragma unroll
        for (int nt = 0; nt < 8; nt++) {
            uint2 bh = sWh[(ks * 8 + nt) * 32 + lane];
            uint2 bl = sWl[(ks * 8 + nt) * 32 + lane];
            asm volatile(
                "mma.sync.aligned.m16n8k8.row.col.f32.tf32.tf32.f32 "
                "{%0,%1,%2,%3}, {%4,%5,%6,%7}, {%8,%9}, {%0,%1,%2,%3};"
                : "+f"(c[nt][0]), "+f"(c[nt][1]), "+f"(c[nt][2]), "+f"(c[nt][3])
                : "r"(a0h), "r"(a1h), "r"(a2h), "r"(a3h), "r"(bh.x), "r"(bh.y));
            asm volatile(
                "mma.sync.aligned.m16n8k8.row.col.f32.tf32.tf32.f32 "
                "{%0,%1,%2,%3}, {%4,%5,%6,%7}, {%8,%9}, {%0,%1,%2,%3};"
                : "+f"(c[nt][0]), "+f"(c[nt][1]), "+f"(c[nt][2]), "+f"(c[nt][3])
                : "r"(a0l), "r"(a1l), "r"(a2l), "r"(a3l), "r"(bh.x), "r"(bh.y));
            asm volatile(
                "mma.sync.aligned.m16n8k8.row.col.f32.tf32.tf32.f32 "
                "{%0,%1,%2,%3}, {%4,%5,%6,%7}, {%8,%9}, {%0,%1,%2,%3};"
                : "+f"(c[nt][0]), "+f"(c[nt][1]), "+f"(c[nt][2]), "+f"(c[nt][3])
                : "r"(a0h), "r"(a1h), "r"(a2h), "r"(a3h), "r"(bl.x), "r"(bl.y));
        }
    }

    // epilogue: store fp16 xw + compute a_s/a_d dots from fp32 accumulators
    float ps0 = 0.f, pd0 = 0.f, ps1 = 0.f, pd1 = 0.f;
    #pragma unroll
    for (int nt = 0; nt < 8; nt++) {
        int col = nt * 8 + 2 * q;
        float sa0 = s_as[col], sa1 = s_as[col + 1];
        float sd0 = s_ad[col], sd1 = s_ad[col + 1];
        ps0 += c[nt][0] * sa0 + c[nt][1] * sa1;
        pd0 += c[nt][0] * sd0 + c[nt][1] * sd1;
        ps1 += c[nt][2] * sa0 + c[nt][3] * sa1;
        pd1 += c[nt][2] * sd0 + c[nt][3] * sd1;
        if (v0) g_xwh[row0 * 32 + nt * 4 + q] = __floats2half2_rn(c[nt][0], c[nt][1]);
        if (v1) g_xwh[row1 * 32 + nt * 4 + q] = __floats2half2_rn(c[nt][2], c[nt][3]);
    }
    #pragma unroll
    for (int o = 1; o < 4; o <<= 1) {
        ps0 += __shfl_xor_sync(0xffffffffu, ps0, o);
        pd0 += __shfl_xor_sync(0xffffffffu, pd0, o);
        ps1 += __shfl_xor_sync(0xffffffffu, ps1, o);
        pd1 += __shfl_xor_sync(0xffffffffu, pd1, o);
    }
    if (q == 0) {
        if (v0) { g_as[row0] = ps0; g_ad[row0] = pd0; }
        if (v1) { g_as[row1] = ps1; g_ad[row1] = pd1; }
    }
}

// ---------------- per-layer: fused softmax attention + aggregation ------------
__global__ void gat_edge_kernel(const float* __restrict__ We,
                                const float* __restrict__ aedge,
                                const float* __restrict__ bias,
                                float* __restrict__ out, int n)
{
    const unsigned F = 0xffffffffu;
    int lane = threadIdx.x & 31, wid = threadIdx.x >> 5;
    float cp = We[2 * lane] * aedge[2 * lane] + We[2 * lane + 1] * aedge[2 * lane + 1];
    #pragma unroll
    for (int o = 16; o; o >>= 1) cp += __shfl_xor_sync(F, cp, o);
    float c = cp;

    const uint2* xh = (const uint2*)g_xwh;
    float4* out4 = (float4*)out;
    int nwarps = (blockDim.x >> 5) * gridDim.x;
    int p = lane & 15;
    int half = lane >> 4;

    for (int node = blockIdx.x * (blockDim.x >> 5) + wid; node < n; node += nwarps) {
        int rs = node * STRIDE;
        int len = g_cursor[node];           // deg + 1 (incl. self-loop), <= 128
        int re = rs + len;
        float adn = g_ad[node];

        float a[4]; int srcs[4];
        float mx = -1e30f;
        #pragma unroll
        for (int s = 0; s < 4; s++) {
            int i = rs + s * 32 + lane;
            float al = -1e30f; int sv = 0;
            if (i < re) {
                int2 se = __ldg(&g_se[i]);
                sv = se.x;
                al = g_as[sv] + adn + c * __int_as_float(se.y);
                al = (al > 0.0f) ? al : 0.2f * al;
            }
            a[s] = al; srcs[s] = sv;
            mx = fmaxf(mx, al);
        }
        #pragma unroll
        for (int o = 16; o; o >>= 1) mx = fmaxf(mx, __shfl_xor_sync(F, mx, o));

        float sum = 0.0f;
        #pragma unroll
        for (int s = 0; s < 4; s++) {
            int i = rs + s * 32 + lane;
            float e = (i < re) ? expf(a[s] - mx) : 0.0f;
            a[s] = e;
            sum += e;
        }
        #pragma unroll
        for (int o = 16; o; o >>= 1) sum += __shfl_xor_sync(F, sum, o);
        float inv = 1.0f / fmaxf(sum, 1e-16f);

        float4 acc = make_float4(0.f, 0.f, 0.f, 0.f);
        #pragma unroll
        for (int s = 0; s < 4; s++) {
            int base = s * 32;
            if (base >= len) break;
            int m = len - base; if (m > 32) m = 32;
            int j = 0;
            for (; j + 8 <= m; j += 8) {
                float w0 = __shfl_sync(F, a[s], j + half);
                float w1 = __shfl_sync(F, a[s], j + 2 + half);
                float w2 = __shfl_sync(F, a[s], j + 4 + half);
                float w3 = __shfl_sync(F, a[s], j + 6 + half);
                int v0 = __shfl_sync(F, srcs[s], j + half);
                int v1 = __shfl_sync(F, srcs[s], j + 2 + half);
                int v2 = __shfl_sync(F, srcs[s], j + 4 + half);
                int v3 = __shfl_sync(F, srcs[s], j + 6 + half);
                uint2 q0 = xh[v0 * 16 + p];
                uint2 q1 = xh[v1 * 16 + p];
                uint2 q2 = xh[v2 * 16 + p];
                uint2 q3 = xh[v3 * 16 + p];
                float2 l0 = __half22float2(*(__half2*)&q0.x), h0 = __half22float2(*(__half2*)&q0.y);
                float2 l1 = __half22float2(*(__half2*)&q1.x), h1 = __half22float2(*(__half2*)&q1.y);
                float2 l2 = __half22float2(*(__half2*)&q2.x), h2 = __half22float2(*(__half2*)&q2.y);
                float2 l3 = __half22float2(*(__half2*)&q3.x), h3 = __half22float2(*(__half2*)&q3.y);
                acc.x += w0 * l0.x; acc.y += w0 * l0.y; acc.z += w0 * h0.x; acc.w += w0 * h0.y;
                acc.x += w1 * l1.x; acc.y += w1 * l1.y; acc.z += w1 * h1.x; acc.w += w1 * h1.y;
                acc.x += w2 * l2.x; acc.y += w2 * l2.y; acc.z += w2 * h2.x; acc.w += w2 * h2.y;
                acc.x += w3 * l3.x; acc.y += w3 * l3.y; acc.z += w3 * h3.x; acc.w += w3 * h3.y;
            }
            for (; j < m; j += 2) {
                int jj = j + half;
                int sl = (jj < m) ? jj : 0;
                float w = __shfl_sync(F, a[s], sl);
                int   v = __shfl_sync(F, srcs[s], sl);
                if (jj >= m) w = 0.0f;
                uint2 qq = xh[v * 16 + p];
                float2 lo = __half22float2(*(__half2*)&qq.x), hi = __half22float2(*(__half2*)&qq.y);
                acc.x += w * lo.x; acc.y += w * lo.y; acc.z += w * hi.x; acc.w += w * hi.y;
            }
        }
        acc.x += __shfl_xor_sync(F, acc.x, 16);
        acc.y += __shfl_xor_sync(F, acc.y, 16);
        acc.z += __shfl_xor_sync(F, acc.z, 16);
        acc.w += __shfl_xor_sync(F, acc.w, 16);
        if (lane < 16) {
            float4 b4 = ((const float4*)bias)[p];
            out4[node * 16 + p] = make_float4(acc.x * inv + b4.x, acc.y * inv + b4.y,
                                              acc.z * inv + b4.z, acc.w * inv + b4.w);
        }
    }
}

// ---------------- final head (2 nodes / warp) ----------------------------------
__global__ void out_mlp_kernel(const float* __restrict__ Wm1,
                               const float* __restrict__ bm1,
                               const float* __restrict__ Wm2,
                               const float* __restrict__ bm2,
                               const float* __restrict__ feat,
                               float* __restrict__ out, int n)
{
    __shared__ float2 sW1[64 * 32];
    __shared__ float sb1[64], sW2[64 * 24], sb2[24];
    __shared__ float2 hs[8][2][32];
    for (int i = threadIdx.x; i < 64 * 64; i += blockDim.x) ((float*)sW1)[i] = Wm1[i];
    for (int i = threadIdx.x; i < 64 * 24; i += blockDim.x) sW2[i] = Wm2[i];
    if (threadIdx.x < 64) sb1[threadIdx.x] = bm1[threadIdx.x];
    if (threadIdx.x < 24) sb2[threadIdx.x] = bm2[threadIdx.x];
    __syncthreads();

    const float2* feat2 = (const float2*)feat;
    int lane = threadIdx.x & 31, wid = threadIdx.x >> 5;
    int nwarps = (blockDim.x >> 5) * gridDim.x;
    for (int base = (blockIdx.x * (blockDim.x >> 5) + wid) * 2; base < n; base += nwarps * 2) {
        float2 f[2]; float2 hid[2];
        #pragma unroll
        for (int m = 0; m < 2; m++) {
            int node = base + m;
            f[m] = (node < n) ? feat2[node * 32 + lane] : make_float2(0.f, 0.f);
            hid[m] = make_float2(sb1[2 * lane], sb1[2 * lane + 1]);
        }
        #pragma unroll
        for (int k = 0; k < 64; k++) {
            float2 w2 = sW1[k * 32 + lane];
            #pragma unroll
            for (int m = 0; m < 2; m++) {
                float fv = __shfl_sync(0xffffffffu, (k & 1) ? f[m].y : f[m].x, k >> 1);
                hid[m].x += fv * w2.x;
                hid[m].y += fv * w2.y;
            }
        }
        #pragma unroll
        for (int m = 0; m < 2; m++) {
            hid[m].x = siluf(hid[m].x);
            hid[m].y = siluf(hid[m].y);
            hs[wid][m][lane] = hid[m];
        }
        __syncwarp();
        if (lane < 24) {
            #pragma unroll
            for (int m = 0; m < 2; m++) {
                int node = base + m;
                if (node >= n) break;
                float a = sb2[lane];
                #pragma unroll
                for (int k2 = 0; k2 < 32; k2++) {
                    float2 hv = hs[wid][m][k2];
                    a += hv.x * sW2[(2 * k2) * 24 + lane];
                    a += hv.y * sW2[(2 * k2 + 1) * 24 + lane];
                }
                out[node * 24 + lane] = a;
            }
        }
        __syncwarp();
    }
}

// ---------------- launch --------------------------------------------------------
extern "C" void kernel_launch(void* const* d_in, const int* in_sizes, int n_in,
                              void* d_out, int out_size)
{
    const float*     x   = (const float*)d_in[0];
    const float*     h   = (const float*)d_in[1];
    const float*     ea  = (const float*)d_in[2];
    const void*      ei  = d_in[3];
    const float *Wx1 = (const float*)d_in[4],  *bx1 = (const float*)d_in[5];
    const float *Wx2 = (const float*)d_in[6],  *bx2 = (const float*)d_in[7];
    const float *Wh1 = (const float*)d_in[8],  *bh1 = (const float*)d_in[9];
    const float *Wh2 = (const float*)d_in[10], *bh2 = (const float*)d_in[11];
    const float *gW  = (const float*)d_in[12];
    const float *gas = (const float*)d_in[13];
    const float *gad = (const float*)d_in[14];
    const float *gae = (const float*)d_in[15];
    const float *gWe = (const float*)d_in[16];
    const float *gb  = (const float*)d_in[17];
    const float *Wm1 = (const float*)d_in[18], *bm1 = (const float*)d_in[19];
    const float *Wm2 = (const float*)d_in[20], *bm2 = (const float*)d_in[21];
    float* out = (float*)d_out;

    const int n = in_sizes[0] / 3;
    const int E = in_sizes[2];

    float* feat0; cudaGetSymbolAddress((void**)&feat0, g_feat0);
    float* feat1; cudaGetSymbolAddress((void**)&feat1, g_feat1);

    const int TB = 256;
    const int WARP_BLOCKS = 1480;

    // node_mlp carries init + dtype probe; must precede scatter.
    node_mlp_kernel<<<WARP_BLOCKS, TB>>>((const unsigned int*)ei, x, h,
                                         Wx1, bx1, Wx2, bx2, Wh1, bh1, Wh2, bh2, feat0, n);
    scatter_kernel<<<(E + TB - 1) / TB, TB>>>((const int*)ei, ea, E, n);
    selfloop_kernel<<<(n + TB - 1) / TB, TB>>>(n);

    float* fin = feat0;
    float* fout = feat1;
    for (int l = 0; l < 3; l++) {
        xw_mma_kernel<<<(n + 127) / 128, TB>>>(gW + l * 64 * 64, gas + l * 64, gad + l * 64, fin, n);
        gat_edge_kernel<<<(n + 7) / 8, TB>>>(gWe + l * 64, gae + l * 64, gb + l * 64, fout, n);
        float* t = fin; fin = fout; fout = t;
    }
    out_mlp_kernel<<<WARP_BLOCKS, TB>>>(Wm1, bm1, Wm2, bm2, fin, out, n);
}

// round 15
// speedup vs baseline: 1.1576x; 1.0011x over previous
#include <cuda_runtime.h>
#include <cuda_bf16.h>
#include <cuda_fp16.h>
#include <math.h>

#define MAXN 50000
#define STRIDE 128                  // fixed CSR row stride (max deg+self ≤ 128)

// ---------------- static device scratch --------------------------------------
__device__ __align__(16) float   g_feat0[MAXN * 64];
__device__ __align__(16) float   g_feat1[MAXN * 64];
__device__ __align__(16) __half2 g_xwh[MAXN * 32];   // fp16 xw rows (64 halves/node)
__device__ float g_as[MAXN];
__device__ float g_ad[MAXN];
__device__ float g_asum[MAXN];
__device__ int   g_cursor[MAXN];
__device__ int2  g_se[MAXN * STRIDE];   // fixed-stride CSR: (src, attr_bits)
__device__ int   g_is64;

__device__ __forceinline__ float siluf(float v) {
    return v / (1.0f + expf(-v));
}

__device__ __forceinline__ int load_idx32(const int* ei32, long long pos, int is64) {
    return ei32[is64 ? 2 * pos : pos];
}

__device__ __forceinline__ unsigned f2tf32(float v) {
    unsigned r;
    asm("cvt.rna.tf32.f32 %0, %1;" : "=r"(r) : "f"(v));
    return r;
}

// ---------------- node MLPs + fused init/dtype-probe ---------------------------
__global__ void node_mlp_kernel(
    const unsigned int* __restrict__ eiw,
    const float* __restrict__ x, const float* __restrict__ h,
    const float* __restrict__ Wx1, const float* __restrict__ bx1,
    const float* __restrict__ Wx2, const float* __restrict__ bx2,
    const float* __restrict__ Wh1, const float* __restrict__ bh1,
    const float* __restrict__ Wh2, const float* __restrict__ bh2,
    float* __restrict__ feat, int n)
{
    // fused init: zero cursors/asum (grid-stride over nodes)
    for (int i = blockIdx.x * blockDim.x + threadIdx.x; i < n; i += blockDim.x * gridDim.x) {
        g_cursor[i] = 0;
        g_asum[i] = 0.0f;
    }
    // dtype probe (block 0, warp 0)
    if (blockIdx.x == 0 && threadIdx.x < 32) {
        int lane = threadIdx.x;
        unsigned bad = 0;
        #pragma unroll
        for (int k = 0; k < 2; k++) bad |= (eiw[2 * (lane + 32 * k) + 1] != 0u);
        unsigned any = __ballot_sync(0xffffffffu, bad);
        if (lane == 0) g_is64 = (any == 0u);
    }

    __shared__ float sWx1[3 * 64], sbx1[64], sbx2[32];
    __shared__ float sWh1[5 * 64], sbh1[64], sbh2[32];
    __shared__ float2 sWx2[64 * 16], sWh2[64 * 16];
    for (int i = threadIdx.x; i < 3 * 64; i += blockDim.x) sWx1[i] = Wx1[i];
    for (int i = threadIdx.x; i < 5 * 64; i += blockDim.x) sWh1[i] = Wh1[i];
    for (int i = threadIdx.x; i < 64 * 32; i += blockDim.x) {
        ((float*)sWx2)[i] = Wx2[i];
        ((float*)sWh2)[i] = Wh2[i];
    }
    if (threadIdx.x < 64) { sbx1[threadIdx.x] = bx1[threadIdx.x]; sbh1[threadIdx.x] = bh1[threadIdx.x]; }
    if (threadIdx.x < 32) { sbx2[threadIdx.x] = bx2[threadIdx.x]; sbh2[threadIdx.x] = bh2[threadIdx.x]; }
    __syncthreads();

    int lane = threadIdx.x & 31, wid = threadIdx.x >> 5;
    int nwarps = (blockDim.x >> 5) * gridDim.x;
    float2* feat2 = (float2*)feat;

    for (int base = (blockIdx.x * (blockDim.x >> 5) + wid) * 2; base < n; base += nwarps * 2) {
        float ha[2], hb[2], ga[2], gb[2];
        #pragma unroll
        for (int m = 0; m < 2; m++) {
            int node = base + m;
            if (node < n) {
                float x0 = x[node * 3 + 0], x1 = x[node * 3 + 1], x2 = x[node * 3 + 2];
                ha[m] = siluf(x0 * sWx1[lane] + x1 * sWx1[64 + lane] + x2 * sWx1[128 + lane] + sbx1[lane]);
                hb[m] = siluf(x0 * sWx1[32 + lane] + x1 * sWx1[96 + lane] + x2 * sWx1[160 + lane] + sbx1[32 + lane]);
                float h0 = h[node * 5 + 0], h1 = h[node * 5 + 1], h2 = h[node * 5 + 2],
                      h3 = h[node * 5 + 3], h4 = h[node * 5 + 4];
                ga[m] = siluf(h0 * sWh1[lane] + h1 * sWh1[64 + lane] + h2 * sWh1[128 + lane]
                            + h3 * sWh1[192 + lane] + h4 * sWh1[256 + lane] + sbh1[lane]);
                gb[m] = siluf(h0 * sWh1[32 + lane] + h1 * sWh1[96 + lane] + h2 * sWh1[160 + lane]
                            + h3 * sWh1[224 + lane] + h4 * sWh1[288 + lane] + sbh1[32 + lane]);
            } else {
                ha[m] = hb[m] = ga[m] = gb[m] = 0.f;
            }
        }
        float2 accx[2] = {make_float2(0.f, 0.f), make_float2(0.f, 0.f)};
        float2 acch[2] = {make_float2(0.f, 0.f), make_float2(0.f, 0.f)};
        int pl = lane & 15;
        #pragma unroll
        for (int k = 0; k < 64; k++) {
            float2 wx = sWx2[k * 16 + pl];
            float2 wh = sWh2[k * 16 + pl];
            #pragma unroll
            for (int m = 0; m < 2; m++) {
                float hvx = __shfl_sync(0xffffffffu, (k < 32) ? ha[m] : hb[m], k & 31);
                float hvh = __shfl_sync(0xffffffffu, (k < 32) ? ga[m] : gb[m], k & 31);
                accx[m].x += hvx * wx.x; accx[m].y += hvx * wx.y;
                acch[m].x += hvh * wh.x; acch[m].y += hvh * wh.y;
            }
        }
        #pragma unroll
        for (int m = 0; m < 2; m++) {
            int node = base + m;
            if (node >= n) break;
            if (lane < 16) {
                feat2[node * 32 + pl] = make_float2(accx[m].x + sbx2[2 * pl], accx[m].y + sbx2[2 * pl + 1]);
            } else {
                feat2[node * 32 + 16 + pl] = make_float2(acch[m].x + sbh2[2 * pl], acch[m].y + sbh2[2 * pl + 1]);
            }
        }
    }
}

// ---------------- CSR build: direct scatter + attr-sum atomics ----------------
__global__ void scatter_kernel(const int* __restrict__ ei32,
                               const float* __restrict__ ea, int E, int n)
{
    int is64 = g_is64;
    int t = blockIdx.x * blockDim.x + threadIdx.x;
    if (t < E) {
        int d = load_idx32(ei32, (long long)E + t, is64);
        int s = load_idx32(ei32, t, is64);
        if ((unsigned)d < (unsigned)n && (unsigned)s < (unsigned)n) {
            float attr = __ldg(&ea[t]);
            int pos = atomicAdd(&g_cursor[d], 1);
            atomicAdd(&g_asum[d], attr);
            if (pos < STRIDE - 1)
                g_se[d * STRIDE + pos] = make_int2(s, __float_as_int(attr));
        }
    }
}

// ---------------- per-layer: xw = feat @ W via compensated TF32 MMA -----------
// 3-MMA split: c += ah*wh + al*wh + ah*wl. Layer 0 additionally appends the
// self-loop CSR entries (grid-stride prologue; was its own kernel).
__global__ void xw_mma_kernel(const float* __restrict__ W,
                              const float* __restrict__ asrc,
                              const float* __restrict__ adst,
                              const float* __restrict__ feat, int n,
                              int do_selfloop)
{
    if (do_selfloop) {
        for (int i = blockIdx.x * blockDim.x + threadIdx.x; i < n; i += blockDim.x * gridDim.x) {
            int deg = g_cursor[i];
            if (deg > STRIDE - 1) deg = STRIDE - 1;
            float mean = g_asum[i] / fmaxf((float)deg, 1.0f);
            g_se[i * STRIDE + deg] = make_int2(i, __float_as_int(mean));
            g_cursor[i] = deg + 1;
        }
    }

    __shared__ uint2 sWh[64 * 32], sWl[64 * 32];
    __shared__ float s_as[64], s_ad[64];
    {
        int tid = threadIdx.x;
        for (int idx = tid; idx < 4096; idx += blockDim.x) {
            int k = idx >> 6, nn = idx & 63;
            int kstep = k >> 3, kr = k & 7;
            int nt = nn >> 3, nc = nn & 7;
            int lane_t = nc * 4 + (kr & 3);
            float w = W[k * 64 + nn];
            unsigned hi = f2tf32(w);
            unsigned lo = f2tf32(w - __uint_as_float(hi));
            int slot = (kstep * 8 + nt) * 32 + lane_t;
            int sub = (kr >> 2) & 1;
            ((unsigned*)&sWh[slot])[sub] = hi;
            ((unsigned*)&sWl[slot])[sub] = lo;
        }
        if (tid < 64) { s_as[tid] = asrc[tid]; s_ad[tid] = adst[tid]; }
    }
    __syncthreads();

    int lane = threadIdx.x & 31, warp = threadIdx.x >> 5;
    int q = lane & 3;
    int g = lane >> 2;
    int row0 = blockIdx.x * 128 + warp * 16 + g;
    int row1 = row0 + 8;
    bool v0 = row0 < n, v1 = row1 < n;

    float c[8][4];
    #pragma unroll
    for (int t = 0; t < 8; t++) { c[t][0] = c[t][1] = c[t][2] = c[t][3] = 0.f; }

    const float* f0p = feat + (long long)row0 * 64;
    const float* f1p = feat + (long long)row1 * 64;

    #pragma unroll
    for (int ks = 0; ks < 8; ks++) {
        int col = ks * 8 + q;
        float av0 = v0 ? f0p[col]     : 0.f;
        float av1 = v1 ? f1p[col]     : 0.f;
        float av2 = v0 ? f0p[col + 4] : 0.f;
        float av3 = v1 ? f1p[col + 4] : 0.f;
        unsigned a0h = f2tf32(av0), a1h = f2tf32(av1), a2h = f2tf32(av2), a3h = f2tf32(av3);
        unsigned a0l = f2tf32(av0 - __uint_as_float(a0h));
        unsigned a1l = f2tf32(av1 - __uint_as_float(a1h));
        unsigned a2l = f2tf32(av2 - __uint_as_float(a2h));
        unsigned a3l = f2tf32(av3 - __uint_as_float(a3h));
        #pragma unroll
        for (int nt = 0; nt < 8; nt++) {
            uint2 bh = sWh[(ks * 8 + nt) * 32 + lane];
            uint2 bl = sWl[(ks * 8 + nt) * 32 + lane];
            asm volatile(
                "mma.sync.aligned.m16n8k8.row.col.f32.tf32.tf32.f32 "
                "{%0,%1,%2,%3}, {%4,%5,%6,%7}, {%8,%9}, {%0,%1,%2,%3};"
                : "+f"(c[nt][0]), "+f"(c[nt][1]), "+f"(c[nt][2]), "+f"(c[nt][3])
                : "r"(a0h), "r"(a1h), "r"(a2h), "r"(a3h), "r"(bh.x), "r"(bh.y));
            asm volatile(
                "mma.sync.aligned.m16n8k8.row.col.f32.tf32.tf32.f32 "
                "{%0,%1,%2,%3}, {%4,%5,%6,%7}, {%8,%9}, {%0,%1,%2,%3};"
                : "+f"(c[nt][0]), "+f"(c[nt][1]), "+f"(c[nt][2]), "+f"(c[nt][3])
                : "r"(a0l), "r"(a1l), "r"(a2l), "r"(a3l), "r"(bh.x), "r"(bh.y));
            asm volatile(
                "mma.sync.aligned.m16n8k8.row.col.f32.tf32.tf32.f32 "
                "{%0,%1,%2,%3}, {%4,%5,%6,%7}, {%8,%9}, {%0,%1,%2,%3};"
                : "+f"(c[nt][0]), "+f"(c[nt][1]), "+f"(c[nt][2]), "+f"(c[nt][3])
                : "r"(a0h), "r"(a1h), "r"(a2h), "r"(a3h), "r"(bl.x), "r"(bl.y));
        }
    }

    float ps0 = 0.f, pd0 = 0.f, ps1 = 0.f, pd1 = 0.f;
    #pragma unroll
    for (int nt = 0; nt < 8; nt++) {
        int col = nt * 8 + 2 * q;
        float sa0 = s_as[col], sa1 = s_as[col + 1];
        float sd0 = s_ad[col], sd1 = s_ad[col + 1];
        ps0 += c[nt][0] * sa0 + c[nt][1] * sa1;
        pd0 += c[nt][0] * sd0 + c[nt][1] * sd1;
        ps1 += c[nt][2] * sa0 + c[nt][3] * sa1;
        pd1 += c[nt][2] * sd0 + c[nt][3] * sd1;
        if (v0) g_xwh[row0 * 32 + nt * 4 + q] = __floats2half2_rn(c[nt][0], c[nt][1]);
        if (v1) g_xwh[row1 * 32 + nt * 4 + q] = __floats2half2_rn(c[nt][2], c[nt][3]);
    }
    #pragma unroll
    for (int o = 1; o < 4; o <<= 1) {
        ps0 += __shfl_xor_sync(0xffffffffu, ps0, o);
        pd0 += __shfl_xor_sync(0xffffffffu, pd0, o);
        ps1 += __shfl_xor_sync(0xffffffffu, ps1, o);
        pd1 += __shfl_xor_sync(0xffffffffu, pd1, o);
    }
    if (q == 0) {
        if (v0) { g_as[row0] = ps0; g_ad[row0] = pd0; }
        if (v1) { g_as[row1] = ps1; g_ad[row1] = pd1; }
    }
}

// ---------------- per-layer: fused softmax attention + aggregation ------------
__global__ void gat_edge_kernel(const float* __restrict__ We,
                                const float* __restrict__ aedge,
                                const float* __restrict__ bias,
                                float* __restrict__ out, int n)
{
    const unsigned F = 0xffffffffu;
    int lane = threadIdx.x & 31, wid = threadIdx.x >> 5;
    float cp = We[2 * lane] * aedge[2 * lane] + We[2 * lane + 1] * aedge[2 * lane + 1];
    #pragma unroll
    for (int o = 16; o; o >>= 1) cp += __shfl_xor_sync(F, cp, o);
    float c = cp;

    const uint2* xh = (const uint2*)g_xwh;
    float4* out4 = (float4*)out;
    int nwarps = (blockDim.x >> 5) * gridDim.x;
    int p = lane & 15;
    int half = lane >> 4;

    for (int node = blockIdx.x * (blockDim.x >> 5) + wid; node < n; node += nwarps) {
        int rs = node * STRIDE;
        int len = g_cursor[node];           // deg + 1 (incl. self-loop), <= 128
        int re = rs + len;
        float adn = g_ad[node];

        float a[4]; int srcs[4];
        float mx = -1e30f;
        #pragma unroll
        for (int s = 0; s < 4; s++) {
            int i = rs + s * 32 + lane;
            float al = -1e30f; int sv = 0;
            if (i < re) {
                int2 se = __ldg(&g_se[i]);
                sv = se.x;
                al = g_as[sv] + adn + c * __int_as_float(se.y);
                al = (al > 0.0f) ? al : 0.2f * al;
            }
            a[s] = al; srcs[s] = sv;
            mx = fmaxf(mx, al);
        }
        #pragma unroll
        for (int o = 16; o; o >>= 1) mx = fmaxf(mx, __shfl_xor_sync(F, mx, o));

        float sum = 0.0f;
        #pragma unroll
        for (int s = 0; s < 4; s++) {
            int i = rs + s * 32 + lane;
            float e = (i < re) ? expf(a[s] - mx) : 0.0f;
            a[s] = e;
            sum += e;
        }
        #pragma unroll
        for (int o = 16; o; o >>= 1) sum += __shfl_xor_sync(F, sum, o);
        float inv = 1.0f / fmaxf(sum, 1e-16f);

        float4 acc = make_float4(0.f, 0.f, 0.f, 0.f);
        #pragma unroll
        for (int s = 0; s < 4; s++) {
            int base = s * 32;
            if (base >= len) break;
            int m = len - base; if (m > 32) m = 32;
            int j = 0;
            for (; j + 8 <= m; j += 8) {
                float w0 = __shfl_sync(F, a[s], j + half);
                float w1 = __shfl_sync(F, a[s], j + 2 + half);
                float w2 = __shfl_sync(F, a[s], j + 4 + half);
                float w3 = __shfl_sync(F, a[s], j + 6 + half);
                int v0 = __shfl_sync(F, srcs[s], j + half);
                int v1 = __shfl_sync(F, srcs[s], j + 2 + half);
                int v2 = __shfl_sync(F, srcs[s], j + 4 + half);
                int v3 = __shfl_sync(F, srcs[s], j + 6 + half);
                uint2 q0 = xh[v0 * 16 + p];
                uint2 q1 = xh[v1 * 16 + p];
                uint2 q2 = xh[v2 * 16 + p];
                uint2 q3 = xh[v3 * 16 + p];
                float2 l0 = __half22float2(*(__half2*)&q0.x), h0 = __half22float2(*(__half2*)&q0.y);
                float2 l1 = __half22float2(*(__half2*)&q1.x), h1 = __half22float2(*(__half2*)&q1.y);
                float2 l2 = __half22float2(*(__half2*)&q2.x), h2 = __half22float2(*(__half2*)&q2.y);
                float2 l3 = __half22float2(*(__half2*)&q3.x), h3 = __half22float2(*(__half2*)&q3.y);
                acc.x += w0 * l0.x; acc.y += w0 * l0.y; acc.z += w0 * h0.x; acc.w += w0 * h0.y;
                acc.x += w1 * l1.x; acc.y += w1 * l1.y; acc.z += w1 * h1.x; acc.w += w1 * h1.y;
                acc.x += w2 * l2.x; acc.y += w2 * l2.y; acc.z += w2 * h2.x; acc.w += w2 * h2.y;
                acc.x += w3 * l3.x; acc.y += w3 * l3.y; acc.z += w3 * h3.x; acc.w += w3 * h3.y;
            }
            for (; j < m; j += 2) {
                int jj = j + half;
                int sl = (jj < m) ? jj : 0;
                float w = __shfl_sync(F, a[s], sl);
                int   v = __shfl_sync(F, srcs[s], sl);
                if (jj >= m) w = 0.0f;
                uint2 qq = xh[v * 16 + p];
                float2 lo = __half22float2(*(__half2*)&qq.x), hi = __half22float2(*(__half2*)&qq.y);
                acc.x += w * lo.x; acc.y += w * lo.y; acc.z += w * hi.x; acc.w += w * hi.y;
            }
        }
        acc.x += __shfl_xor_sync(F, acc.x, 16);
        acc.y += __shfl_xor_sync(F, acc.y, 16);
        acc.z += __shfl_xor_sync(F, acc.z, 16);
        acc.w += __shfl_xor_sync(F, acc.w, 16);
        if (lane < 16) {
            float4 b4 = ((const float4*)bias)[p];
            out4[node * 16 + p] = make_float4(acc.x * inv + b4.x, acc.y * inv + b4.y,
                                              acc.z * inv + b4.z, acc.w * inv + b4.w);
        }
    }
}

// ---------------- final head (2 nodes / warp) ----------------------------------
__global__ void out_mlp_kernel(const float* __restrict__ Wm1,
                               const float* __restrict__ bm1,
                               const float* __restrict__ Wm2,
                               const float* __restrict__ bm2,
                               const float* __restrict__ feat,
                               float* __restrict__ out, int n)
{
    __shared__ float2 sW1[64 * 32];
    __shared__ float sb1[64], sW2[64 * 24], sb2[24];
    __shared__ float2 hs[8][2][32];
    for (int i = threadIdx.x; i < 64 * 64; i += blockDim.x) ((float*)sW1)[i] = Wm1[i];
    for (int i = threadIdx.x; i < 64 * 24; i += blockDim.x) sW2[i] = Wm2[i];
    if (threadIdx.x < 64) sb1[threadIdx.x] = bm1[threadIdx.x];
    if (threadIdx.x < 24) sb2[threadIdx.x] = bm2[threadIdx.x];
    __syncthreads();

    const float2* feat2 = (const float2*)feat;
    int lane = threadIdx.x & 31, wid = threadIdx.x >> 5;
    int nwarps = (blockDim.x >> 5) * gridDim.x;
    for (int base = (blockIdx.x * (blockDim.x >> 5) + wid) * 2; base < n; base += nwarps * 2) {
        float2 f[2]; float2 hid[2];
        #pragma unroll
        for (int m = 0; m < 2; m++) {
            int node = base + m;
            f[m] = (node < n) ? feat2[node * 32 + lane] : make_float2(0.f, 0.f);
            hid[m] = make_float2(sb1[2 * lane], sb1[2 * lane + 1]);
        }
        #pragma unroll
        for (int k = 0; k < 64; k++) {
            float2 w2 = sW1[k * 32 + lane];
            #pragma unroll
            for (int m = 0; m < 2; m++) {
                float fv = __shfl_sync(0xffffffffu, (k & 1) ? f[m].y : f[m].x, k >> 1);
                hid[m].x += fv * w2.x;
                hid[m].y += fv * w2.y;
            }
        }
        #pragma unroll
        for (int m = 0; m < 2; m++) {
            hid[m].x = siluf(hid[m].x);
            hid[m].y = siluf(hid[m].y);
            hs[wid][m][lane] = hid[m];
        }
        __syncwarp();
        if (lane < 24) {
            #pragma unroll
            for (int m = 0; m < 2; m++) {
                int node = base + m;
                if (node >= n) break;
                float a = sb2[lane];
                #pragma unroll
                for (int k2 = 0; k2 < 32; k2++) {
                    float2 hv = hs[wid][m][k2];
                    a += hv.x * sW2[(2 * k2) * 24 + lane];
                    a += hv.y * sW2[(2 * k2 + 1) * 24 + lane];
                }
                out[node * 24 + lane] = a;
            }
        }
        __syncwarp();
    }
}

// ---------------- launch --------------------------------------------------------
extern "C" void kernel_launch(void* const* d_in, const int* in_sizes, int n_in,
                              void* d_out, int out_size)
{
    const float*     x   = (const float*)d_in[0];
    const float*     h   = (const float*)d_in[1];
    const float*     ea  = (const float*)d_in[2];
    const void*      ei  = d_in[3];
    const float *Wx1 = (const float*)d_in[4],  *bx1 = (const float*)d_in[5];
    const float *Wx2 = (const float*)d_in[6],  *bx2 = (const float*)d_in[7];
    const float *Wh1 = (const float*)d_in[8],  *bh1 = (const float*)d_in[9];
    const float *Wh2 = (const float*)d_in[10], *bh2 = (const float*)d_in[11];
    const float *gW  = (const float*)d_in[12];
    const float *gas = (const float*)d_in[13];
    const float *gad = (const float*)d_in[14];
    const float *gae = (const float*)d_in[15];
    const float *gWe = (const float*)d_in[16];
    const float *gb  = (const float*)d_in[17];
    const float *Wm1 = (const float*)d_in[18], *bm1 = (const float*)d_in[19];
    const float *Wm2 = (const float*)d_in[20], *bm2 = (const float*)d_in[21];
    float* out = (float*)d_out;

    const int n = in_sizes[0] / 3;
    const int E = in_sizes[2];

    float* feat0; cudaGetSymbolAddress((void**)&feat0, g_feat0);
    float* feat1; cudaGetSymbolAddress((void**)&feat1, g_feat1);

    const int TB = 256;
    const int WARP_BLOCKS = 1480;

    // node_mlp carries init + dtype probe; must precede scatter.
    node_mlp_kernel<<<WARP_BLOCKS, TB>>>((const unsigned int*)ei, x, h,
                                         Wx1, bx1, Wx2, bx2, Wh1, bh1, Wh2, bh2, feat0, n);
    scatter_kernel<<<(E + TB - 1) / TB, TB>>>((const int*)ei, ea, E, n);

    float* fin = feat0;
    float* fout = feat1;
    for (int l = 0; l < 3; l++) {
        // layer 0's xw kernel also appends self-loop CSR entries (prologue)
        xw_mma_kernel<<<(n + 127) / 128, TB>>>(gW + l * 64 * 64, gas + l * 64, gad + l * 64,
                                               fin, n, l == 0 ? 1 : 0);
        gat_edge_kernel<<<(n + 7) / 8, TB>>>(gWe + l * 64, gae + l * 64, gb + l * 64, fout, n);
        float* t = fin; fin = fout; fout = t;
    }
    out_mlp_kernel<<<WARP_BLOCKS, TB>>>(Wm1, bm1, Wm2, bm2, fin, out, n);
}